// round 14
// baseline (speedup 1.0000x reference)
#include <cuda_runtime.h>
#include <cuda_fp16.h>
#include <cstdint>

#define GRID  64
#define NTHR  512
#define BSZ   128
#define TE    512
#define HD    256
#define MELD  80
#define RF    5
#define STEPS 200
#define G3    768

// ---- smem float offsets (decode loop); prelude staging overlays the same buffer ----
#define O_HA   0
#define O_H1   512
#define O_H2   1024
#define O_D    1536
#define O_Q    2048
#define O_DD   2560
#define O_P    3072
#define O_IN2  3584
#define O_S    4096
#define O_HN   4608
#define O_GI   5120   // [2][768]
#define O_SEXP 6656   // [2][512]
#define O_RED  7680   // 32
#define O_PACC 7712   // [2][2][256] = 1024
#define O_V    8736   // 256
#define SMEM_FLOATS 8992
#define SMEM_BYTES  (SMEM_FLOATS * 4)   // 35,968 B  (prelude staging needs 33,280)

// ---------------- device scratch -----------------------------------------------------
__device__ __half g_w1h[(size_t)BSZ * TE * HD];
__device__ __half g_ench[(size_t)BSZ * TE * HD];
__device__ float  g_pre1[STEPS * BSZ * HD];
__device__ float  g_xs[STEPS * BSZ * (HD / 2)];
__device__ float  g_giatt[(size_t)STEPS * BSZ * G3];   // [step*128+b][768]
__device__ __half g_w2h[HD * HD];
__device__ __half g_projh[HD * 2 * HD];
__device__ __half g_wih1h[G3 * HD];
__device__ __half g_wih2h[G3 * HD];
__device__ unsigned g_bar_count;
__device__ unsigned g_bar_epoch;

// ---------------- helpers ------------------------------------------------------------
__device__ __forceinline__ float tanh_fast(float x) {
    float y; asm("tanh.approx.f32 %0, %1;" : "=f"(y) : "f"(x)); return y;
}
__device__ __forceinline__ float sigmoidf_(float x) { return 1.f / (1.f + __expf(-x)); }
__device__ __forceinline__ unsigned ld_acq(const unsigned* p) {
    unsigned v; asm volatile("ld.acquire.gpu.b32 %0, [%1];" : "=r"(v) : "l"(p)); return v;
}
__device__ __forceinline__ void gsync(unsigned target)
{
    __syncthreads();
    if (threadIdx.x == 0) {
        __threadfence();
        unsigned a = atomicAdd(&g_bar_count, 1u);
        if (a == GRID - 1u) {
            g_bar_count = 0u;
            __threadfence();
            atomicAdd(&g_bar_epoch, 1u);
        } else {
            while ((int)(ld_acq(&g_bar_epoch) - target) < 0) { }
        }
    }
    __syncthreads();
}
// sum over 16-lane half (both halves reduce independently)
__device__ __forceinline__ float hred16(float v) {
    v += __shfl_xor_sync(0xffffffffu, v, 8);
    v += __shfl_xor_sync(0xffffffffu, v, 4);
    v += __shfl_xor_sync(0xffffffffu, v, 2);
    v += __shfl_xor_sync(0xffffffffu, v, 1);
    return v;
}
// fp32 dot: 16 k-elements (lane slice) of row R against hoisted x regs
__device__ __forceinline__ float dot16f(const float4* __restrict__ R, int l16,
                                        const float4& a0, const float4& a1,
                                        const float4& a2, const float4& a3)
{
    const float4 w0 = R[2 * l16], w1 = R[2 * l16 + 1];
    const float4 w2 = R[32 + 2 * l16], w3 = R[33 + 2 * l16];
    float acc = 0.f;
    acc = fmaf(w0.x, a0.x, acc); acc = fmaf(w0.y, a0.y, acc);
    acc = fmaf(w0.z, a0.z, acc); acc = fmaf(w0.w, a0.w, acc);
    acc = fmaf(w1.x, a1.x, acc); acc = fmaf(w1.y, a1.y, acc);
    acc = fmaf(w1.z, a1.z, acc); acc = fmaf(w1.w, a1.w, acc);
    acc = fmaf(w2.x, a2.x, acc); acc = fmaf(w2.y, a2.y, acc);
    acc = fmaf(w2.z, a2.z, acc); acc = fmaf(w2.w, a2.w, acc);
    acc = fmaf(w3.x, a3.x, acc); acc = fmaf(w3.y, a3.y, acc);
    acc = fmaf(w3.z, a3.z, acc); acc = fmaf(w3.w, a3.w, acc);
    return acc;
}
// 8 halves (one float4 load) dotted against two float4 x regs
__device__ __forceinline__ float dot_h8(float4 wh, const float4& xa, const float4& xb)
{
    const __half2* p = (const __half2*)&wh;
    const float2 f0 = __half22float2(p[0]), f1 = __half22float2(p[1]);
    const float2 f2 = __half22float2(p[2]), f3 = __half22float2(p[3]);
    float acc = 0.f;
    acc = fmaf(f0.x, xa.x, acc); acc = fmaf(f0.y, xa.y, acc);
    acc = fmaf(f1.x, xa.z, acc); acc = fmaf(f1.y, xa.w, acc);
    acc = fmaf(f2.x, xb.x, acc); acc = fmaf(f2.y, xb.y, acc);
    acc = fmaf(f3.x, xb.z, acc); acc = fmaf(f3.y, xb.w, acc);
    return acc;
}

// ---------------- block-local GRU: 16 warps x 16 j; half-warp = one batch ------------
__device__ void block_gru(const float* __restrict__ Whh,
                          const __half* __restrict__ WihH,
                          const float* __restrict__ giS,
                          const float* __restrict__ bih,
                          const float* __restrict__ bhh,
                          const float* __restrict__ hS,
                          const float* __restrict__ xS,
                          float* __restrict__ hnS,
                          float* __restrict__ sumS)
{
    const int w = threadIdx.x >> 5, lane = threadIdx.x & 31;
    const int hf = lane >> 4, l16 = lane & 15;
    const float* hb = hS + hf * 256;
    const float4 h0 = *(const float4*)(hb + 8 * l16);
    const float4 h1 = *(const float4*)(hb + 8 * l16 + 4);
    const float4 h2 = *(const float4*)(hb + 128 + 8 * l16);
    const float4 h3 = *(const float4*)(hb + 128 + 8 * l16 + 4);
    float4 x0, x1, x2, x3;
    if (xS) {
        const float* xb = xS + hf * 256;
        x0 = *(const float4*)(xb + 8 * l16);
        x1 = *(const float4*)(xb + 8 * l16 + 4);
        x2 = *(const float4*)(xb + 128 + 8 * l16);
        x3 = *(const float4*)(xb + 128 + 8 * l16 + 4);
    }
    for (int jj = 0; jj < 16; jj++) {
        const int j = (w << 4) + jj;
        float hr = dot16f((const float4*)(Whh + (size_t)j * 256),        l16, h0, h1, h2, h3);
        float hz = dot16f((const float4*)(Whh + (size_t)(j + 256) * 256), l16, h0, h1, h2, h3);
        float hn = dot16f((const float4*)(Whh + (size_t)(j + 512) * 256), l16, h0, h1, h2, h3);
        hr = hred16(hr); hz = hred16(hz); hn = hred16(hn);
        float ir = 0.f, iz = 0.f, inn = 0.f;
        if (giS) {
            if (l16 == 0) {
                const float* gp = giS + hf * 768 + j;
                ir = gp[0]; iz = gp[256]; inn = gp[512];
            }
        } else {
            const float4* U = (const float4*)(WihH + (size_t)j * 256);
            const float4* V = (const float4*)(WihH + (size_t)(j + 256) * 256);
            const float4* N = (const float4*)(WihH + (size_t)(j + 512) * 256);
            ir  = dot_h8(U[l16], x0, x1) + dot_h8(U[16 + l16], x2, x3);
            iz  = dot_h8(V[l16], x0, x1) + dot_h8(V[16 + l16], x2, x3);
            inn = dot_h8(N[l16], x0, x1) + dot_h8(N[16 + l16], x2, x3);
            ir = hred16(ir); iz = hred16(iz); inn = hred16(inn);
            if (l16 == 0) { ir += bih[j]; iz += bih[j + 256]; inn += bih[j + 512]; }
        }
        if (l16 == 0) {
            const float rg = sigmoidf_(ir + hr + bhh[j]);
            const float zg = sigmoidf_(iz + hz + bhh[j + 256]);
            const float ng = tanhf(inn + rg * (hn + bhh[j + 512]));
            const float hv = hS[hf * 256 + j];
            const float val = (1.f - zg) * ng + zg * hv;
            hnS[hf * 256 + j] = val;
            if (sumS) sumS[hf * 256 + j] = val + xS[hf * 256 + j];
        }
    }
}

// ---------------- q = x @ W2h^T + b (fp16 weights, K=256, 256 outputs) ---------------
__device__ void block_gemv_h(const __half* __restrict__ Wh, const float* __restrict__ bias,
                             const float* __restrict__ xS, float* __restrict__ yS)
{
    const int w = threadIdx.x >> 5, lane = threadIdx.x & 31;
    const int hf = lane >> 4, l16 = lane & 15;
    const float* xb = xS + hf * 256;
    const float4 x0 = *(const float4*)(xb + 8 * l16);
    const float4 x1 = *(const float4*)(xb + 8 * l16 + 4);
    const float4 x2 = *(const float4*)(xb + 128 + 8 * l16);
    const float4 x3 = *(const float4*)(xb + 128 + 8 * l16 + 4);
    for (int jj = 0; jj < 16; jj++) {
        const int j = (w << 4) + jj;
        const float4* U = (const float4*)(Wh + (size_t)j * 256);
        float acc = dot_h8(U[l16], x0, x1) + dot_h8(U[16 + l16], x2, x3);
        acc = hred16(acc);
        if (l16 == 0) yS[hf * 256 + j] = acc + bias[j];
    }
}

// ---------------- p = [d|dd] @ projh^T + b (fp16, K=512) -----------------------------
__device__ void block_proj(const __half* __restrict__ Wh, const float* __restrict__ bias,
                           const float* __restrict__ dS, const float* __restrict__ ddS,
                           float* __restrict__ pS)
{
    const int w = threadIdx.x >> 5, lane = threadIdx.x & 31;
    const int hf = lane >> 4, l16 = lane & 15;
    const float* db = dS + hf * 256;
    const float* eb = ddS + hf * 256;
    const float4 d0 = *(const float4*)(db + 8 * l16);
    const float4 d1 = *(const float4*)(db + 8 * l16 + 4);
    const float4 d2 = *(const float4*)(db + 128 + 8 * l16);
    const float4 d3 = *(const float4*)(db + 128 + 8 * l16 + 4);
    const float4 e0 = *(const float4*)(eb + 8 * l16);
    const float4 e1 = *(const float4*)(eb + 8 * l16 + 4);
    const float4 e2 = *(const float4*)(eb + 128 + 8 * l16);
    const float4 e3 = *(const float4*)(eb + 128 + 8 * l16 + 4);
    for (int jj = 0; jj < 16; jj++) {
        const int j = (w << 4) + jj;
        const float4* U = (const float4*)(Wh + (size_t)j * 512);
        float acc = dot_h8(U[l16],      d0, d1) + dot_h8(U[16 + l16], d2, d3)
                  + dot_h8(U[32 + l16], e0, e1) + dot_h8(U[48 + l16], e2, e3);
        acc = hred16(acc);
        if (l16 == 0) pS[hf * 256 + j] = acc + bias[j];
    }
}

// ---------------- out rows (fp32 weights, 400 outputs) -------------------------------
__device__ void block_out(const float* __restrict__ Wf, const float* __restrict__ bias,
                          const float* __restrict__ sS, float* __restrict__ out,
                          int b0, int step)
{
    const int w = threadIdx.x >> 5, lane = threadIdx.x & 31;
    const int hf = lane >> 4, l16 = lane & 15;
    const float* sb = sS + hf * 256;
    const float4 s0 = *(const float4*)(sb + 8 * l16);
    const float4 s1 = *(const float4*)(sb + 8 * l16 + 4);
    const float4 s2 = *(const float4*)(sb + 128 + 8 * l16);
    const float4 s3 = *(const float4*)(sb + 128 + 8 * l16 + 4);
    for (int jj = 0; jj < 25; jj++) {
        const int j = w * 25 + jj;
        float acc = dot16f((const float4*)(Wf + (size_t)j * 256), l16, s0, s1, s2, s3);
        acc = hred16(acc);
        if (l16 == 0)
            out[(size_t)(b0 + hf) * 80000 + (size_t)step * (RF * MELD) + j]
                = acc + bias[j];
    }
}

// ---------------- attention: scores -> softmax -> context (block-local, 2 batches) ---
__device__ void block_attn(int b0, float vb0, float* __restrict__ sm)
{
    float* qS   = sm + O_Q;
    float* sexp = sm + O_SEXP;
    float* red  = sm + O_RED;
    float* pacc = sm + O_PACC;
    float* ddS  = sm + O_DD;
    const float* vS = sm + O_V;
    const int tid = threadIdx.x, w = tid >> 5, lane = tid & 31;

    // scores: warp -> (batch = w&1, 64 contiguous t)
    {
        const int b = w & 1, tbase = (w >> 1) * 64;
        const float4 q0 = *(const float4*)(qS + b * 256 + lane * 8);
        const float4 q1 = *(const float4*)(qS + b * 256 + lane * 8 + 4);
        const float4 v0 = *(const float4*)(vS + lane * 8);
        const float4 v1 = *(const float4*)(vS + lane * 8 + 4);
        const float4* wb = (const float4*)g_w1h + (size_t)(b0 + b) * TE * 32;
        for (int rr = 0; rr < 64; rr++) {
            const int t = tbase + rr;
            const float4 wv = wb[(size_t)t * 32 + lane];
            const __half2* p = (const __half2*)&wv;
            const float2 f0 = __half22float2(p[0]), f1 = __half22float2(p[1]);
            const float2 f2 = __half22float2(p[2]), f3 = __half22float2(p[3]);
            float acc = v0.x * tanh_fast(f0.x + q0.x) + v0.y * tanh_fast(f0.y + q0.y)
                      + v0.z * tanh_fast(f1.x + q0.z) + v0.w * tanh_fast(f1.y + q0.w)
                      + v1.x * tanh_fast(f2.x + q1.x) + v1.y * tanh_fast(f2.y + q1.y)
                      + v1.z * tanh_fast(f3.x + q1.z) + v1.w * tanh_fast(f3.y + q1.w);
            for (int o = 16; o; o >>= 1) acc += __shfl_down_sync(0xffffffffu, acc, o);
            if (lane == 0) sexp[b * 512 + t] = acc + vb0;
        }
    }
    __syncthreads();

    // softmax per batch (warps 0-7 = b0, 8-15 = b1)
    const int sb = tid >> 8, tl = tid & 255;
    const float s0 = sexp[sb * 512 + tl], s1 = sexp[sb * 512 + 256 + tl];
    float mx = fmaxf(s0, s1);
    for (int o = 16; o; o >>= 1) mx = fmaxf(mx, __shfl_xor_sync(0xffffffffu, mx, o));
    if (lane == 0) red[w] = mx;
    __syncthreads();
    float M = red[sb * 8];
#pragma unroll
    for (int k = 1; k < 8; k++) M = fmaxf(M, red[sb * 8 + k]);
    const float e0 = __expf(s0 - M), e1 = __expf(s1 - M);
    float ss = e0 + e1;
    for (int o = 16; o; o >>= 1) ss += __shfl_xor_sync(0xffffffffu, ss, o);
    __syncthreads();                       // all reads of red done before reuse
    if (lane == 0) red[w] = ss;
    __syncthreads();
    float sum = red[sb * 8];
#pragma unroll
    for (int k = 1; k < 8; k++) sum += red[sb * 8 + k];
    sexp[sb * 512 + tl] = e0;
    sexp[sb * 512 + 256 + tl] = e1;
    if (tid == (sb << 8)) red[24 + sb] = 1.f / sum;
    __syncthreads();

    // context: thread = (h2, batch, t-half); each covers 256 t
    const int h2 = tid & 127, cb = (tid >> 7) & 1, tq = tid >> 8;
    const __half2* e2 = (const __half2*)g_ench
                      + ((size_t)(b0 + cb) * TE + tq * 256) * 128 + h2;
    float ax = 0.f, ay = 0.f;
#pragma unroll 8
    for (int tt = 0; tt < 256; tt++) {
        const float2 v = __half22float2(e2[(size_t)tt * 128]);
        const float u = sexp[cb * 512 + tq * 256 + tt];
        ax = fmaf(u, v.x, ax); ay = fmaf(u, v.y, ay);
    }
    pacc[tq * 512 + cb * 256 + h2 * 2]     = ax;
    pacc[tq * 512 + cb * 256 + h2 * 2 + 1] = ay;
    __syncthreads();
    {
        const int b = tid >> 8, h = tid & 255;
        ddS[b * 256 + h] = (pacc[b * 256 + h] + pacc[512 + b * 256 + h]) * red[24 + b];
    }
    __syncthreads();
}

// ---------------- prelude tiled GEMM (grid-strided) ----------------------------------
__device__ void dev_linear(const float* __restrict__ X, const float* __restrict__ dec,
                           int nf4, const float* __restrict__ W,
                           const float* __restrict__ bias,
                           float* __restrict__ Yf, __half* __restrict__ Yh,
                           int ldy, int relu, int nrt, int ncp, float4* sm4)
{
    const int tid = threadIdx.x, lane = tid & 31, wid = tid >> 5;
    const int stride4 = nf4 + 1;
    const int tiles = nrt * ncp;
    for (int t = blockIdx.x; t < tiles; t += GRID) {
        const int rt = t / ncp, cp = t - rt * ncp;
        const long r0 = (long)rt * 32;
        for (int idx = tid; idx < 32 * nf4; idx += NTHR) {
            int row = idx / nf4, c4 = idx - row * nf4;
            long r = r0 + row;
            float4 v;
            if (dec) v = *(const float4*)(dec + (r & 127) * 80000L
                                          + (r >> 7) * (RF * MELD) + c4 * 4);
            else     v = *(const float4*)(X + r * (long)(nf4 * 4) + c4 * 4);
            sm4[row * stride4 + c4] = v;
        }
        __syncthreads();
        const int j0 = cp * 64 + wid * 4;
        const float4* W4 = (const float4*)W + (size_t)j0 * nf4;
        const float4* xr = sm4 + lane * stride4;
        float a0 = bias[j0], a1 = bias[j0 + 1], a2 = bias[j0 + 2], a3 = bias[j0 + 3];
#pragma unroll 4
        for (int k = 0; k < nf4; k++) {
            const float4 x = xr[k];
            const float4 w0 = W4[k];
            a0 = fmaf(w0.x, x.x, a0); a0 = fmaf(w0.y, x.y, a0);
            a0 = fmaf(w0.z, x.z, a0); a0 = fmaf(w0.w, x.w, a0);
            const float4 w1 = W4[nf4 + k];
            a1 = fmaf(w1.x, x.x, a1); a1 = fmaf(w1.y, x.y, a1);
            a1 = fmaf(w1.z, x.z, a1); a1 = fmaf(w1.w, x.w, a1);
            const float4 w2 = W4[2 * nf4 + k];
            a2 = fmaf(w2.x, x.x, a2); a2 = fmaf(w2.y, x.y, a2);
            a2 = fmaf(w2.z, x.z, a2); a2 = fmaf(w2.w, x.w, a2);
            const float4 w3 = W4[3 * nf4 + k];
            a3 = fmaf(w3.x, x.x, a3); a3 = fmaf(w3.y, x.y, a3);
            a3 = fmaf(w3.z, x.z, a3); a3 = fmaf(w3.w, x.w, a3);
        }
        if (relu) {
            a0 = fmaxf(a0, 0.f); a1 = fmaxf(a1, 0.f);
            a2 = fmaxf(a2, 0.f); a3 = fmaxf(a3, 0.f);
        }
        const long orow = (r0 + lane) * (long)ldy + j0;
        if (Yh) {
            Yh[orow] = __float2half(a0);     Yh[orow + 1] = __float2half(a1);
            Yh[orow + 2] = __float2half(a2); Yh[orow + 3] = __float2half(a3);
        } else {
            Yf[orow] = a0; Yf[orow + 1] = a1; Yf[orow + 2] = a2; Yf[orow + 3] = a3;
        }
        __syncthreads();
    }
}

// ---------------- persistent kernel --------------------------------------------------
__global__ void __launch_bounds__(NTHR, 1)
mel_persist(const float* __restrict__ enc, const float* __restrict__ dec,
            const float* pre_w1, const float* pre_b1,
            const float* pre_w2, const float* pre_b2,
            const float* w1, const float* b1, const float* w2, const float* b2,
            const float* v_w, const float* v_b,
            const float* proj_w, const float* proj_b,
            const float* out_w, const float* out_b,
            const float* att_wih, const float* att_whh,
            const float* att_bih, const float* att_bhh,
            const float* g1_wih, const float* g1_whh,
            const float* g1_bih, const float* g1_bhh,
            const float* g2_wih, const float* g2_whh,
            const float* g2_bih, const float* g2_bhh,
            float* __restrict__ out)
{
    extern __shared__ float smf[];
    const int tid = threadIdx.x;
    const unsigned base = ld_acq(&g_bar_epoch);
    unsigned ep = 0;
#define GS() gsync(base + (++ep))

    // P0: fp16 copies (enc, forward weights)
    {
        const int gtid = blockIdx.x * NTHR + tid;
        const float4* e4 = (const float4*)enc;
        __half2* o2 = (__half2*)g_ench;
        const int n4 = (BSZ * TE * HD) / 4;
        for (int i = gtid; i < n4; i += GRID * NTHR) {
            const float4 v = e4[i];
            o2[2 * i]     = __floats2half2_rn(v.x, v.y);
            o2[2 * i + 1] = __floats2half2_rn(v.z, v.w);
        }
        for (int i = gtid; i < HD * HD; i += GRID * NTHR)      g_w2h[i]   = __float2half(w2[i]);
        for (int i = gtid; i < HD * 2 * HD; i += GRID * NTHR)  g_projh[i] = __float2half(proj_w[i]);
        for (int i = gtid; i < G3 * HD; i += GRID * NTHR)      g_wih1h[i] = __float2half(g1_wih[i]);
        for (int i = gtid; i < G3 * HD; i += GRID * NTHR)      g_wih2h[i] = __float2half(g2_wih[i]);
    }
    // P1..P4 prelude GEMMs
    dev_linear(nullptr, dec, 20, pre_w1, pre_b1, g_pre1, nullptr, HD, 1, 800, 4, (float4*)smf);
    GS();
    dev_linear(g_pre1, nullptr, 64, pre_w2, pre_b2, g_xs, nullptr, 128, 1, 800, 2, (float4*)smf);
    GS();
    dev_linear(g_xs, nullptr, 32, att_wih, att_bih, g_giatt, nullptr, G3, 0, 800, 12, (float4*)smf);
    GS();
    dev_linear(enc, nullptr, 64, w1, b1, nullptr, g_w1h, HD, 0, 2048, 4, (float4*)smf);
    GS();

    // ---- decode loop: fully block-local, zero grid barriers -------------------------
    const int b0 = blockIdx.x * 2;
    for (int idx = tid; idx < 1536; idx += NTHR) smf[O_HA + idx] = 0.f;  // hA,h1,h2
    for (int idx = tid; idx < HD; idx += NTHR)   smf[O_V + idx] = v_w[idx];
    const float vb0 = v_b[0];
    __syncthreads();

    for (int i = 0; i < STEPS; i++) {
        // stage gi for this step's 2 batches
        for (int idx = tid; idx < 1536; idx += NTHR) {
            const int b = idx >= 768, j = idx - b * 768;
            smf[O_GI + idx] = g_giatt[((size_t)i * BSZ + b0 + b) * G3 + j];
        }
        __syncthreads();
        // A: attention GRU (gi precomputed)
        block_gru(att_whh, nullptr, smf + O_GI, nullptr, att_bhh,
                  smf + O_HA, nullptr, smf + O_HN, nullptr);
        __syncthreads();
        for (int idx = tid; idx < 512; idx += NTHR) {
            const float v = smf[O_HN + idx];
            smf[O_HA + idx] = v; smf[O_D + idx] = v;
        }
        __syncthreads();
        // B: q = d @ w2^T + b2 (fp16)
        block_gemv_h(g_w2h, b2, smf + O_D, smf + O_Q);
        __syncthreads();
        // C: attention (internally synced; writes dd)
        block_attn(b0, vb0, smf);
        // D: p = [d|dd] @ proj^T + b (fp16)
        block_proj(g_projh, proj_b, smf + O_D, smf + O_DD, smf + O_P);
        __syncthreads();
        // E: GRU1 (Whh fp32, Wih fp16); in2 = o1 + p
        block_gru(g1_whh, g_wih1h, nullptr, g1_bih, g1_bhh,
                  smf + O_H1, smf + O_P, smf + O_HN, smf + O_IN2);
        __syncthreads();
        for (int idx = tid; idx < 512; idx += NTHR) smf[O_H1 + idx] = smf[O_HN + idx];
        __syncthreads();
        // F: GRU2; s = o2 + in2
        block_gru(g2_whh, g_wih2h, nullptr, g2_bih, g2_bhh,
                  smf + O_H2, smf + O_IN2, smf + O_HN, smf + O_S);
        __syncthreads();
        for (int idx = tid; idx < 512; idx += NTHR) smf[O_H2 + idx] = smf[O_HN + idx];
        __syncthreads();
        // G: out = s @ out_w^T + out_b (fp32 weights; final output precision)
        block_out(out_w, out_b, smf + O_S, out, b0, i);
        __syncthreads();
    }
#undef GS
}

// ---------------- host launch --------------------------------------------------------
extern "C" void kernel_launch(void* const* d_in, const int* in_sizes, int n_in,
                              void* d_out, int out_size)
{
    cudaFuncSetAttribute(mel_persist, cudaFuncAttributeMaxDynamicSharedMemorySize,
                         SMEM_BYTES);
    mel_persist<<<GRID, NTHR, SMEM_BYTES>>>(
        (const float*)d_in[0],  (const float*)d_in[1],
        (const float*)d_in[2],  (const float*)d_in[3],
        (const float*)d_in[4],  (const float*)d_in[5],
        (const float*)d_in[6],  (const float*)d_in[7],
        (const float*)d_in[8],  (const float*)d_in[9],
        (const float*)d_in[10], (const float*)d_in[11],
        (const float*)d_in[12], (const float*)d_in[13],
        (const float*)d_in[14], (const float*)d_in[15],
        (const float*)d_in[16], (const float*)d_in[17],
        (const float*)d_in[18], (const float*)d_in[19],
        (const float*)d_in[20], (const float*)d_in[21],
        (const float*)d_in[22], (const float*)d_in[23],
        (const float*)d_in[24], (const float*)d_in[25],
        (const float*)d_in[26], (const float*)d_in[27],
        (float*)d_out);
}

// round 15
// speedup vs baseline: 1.8831x; 1.8831x over previous
#include <cuda_runtime.h>
#include <cuda_fp16.h>
#include <cstdint>

#define GRID  128
#define NTHR  512
#define BSZ   128
#define TE    512
#define HD    256
#define MELD  80
#define RF    5
#define STEPS 200
#define G3    768

// ---- smem float-offset layout (total 200,768 B) ------------------------------------
#define F_XS    0        // [256][32] activation staging
#define F_HS    8192     // [256][32]
#define F_SCR   16384    // 2064 fl: attn region / K-split partials
#define F_WATT  18448    // 6144 fl: att Whh rows (8 j x 3 gates x 256)
#define F_WG1   24592    // 6144 fl
#define F_WG2   30736    // 6144 fl
#define F_WOUT  36880    // 4096 fl: out rows (8 jp x 2 x 256, zero-padded)
#define F_HALFB 40976    // fp16 region base (float offset)
#define H_WIH1  0        // 6144 halves
#define H_WIH2  6144     // 6144
#define H_W2    12288    // 2048
#define H_PROJ  14336    // 4096
#define SMEM_FLOATS (40976 + 9216)
#define SMEM_BYTES  (SMEM_FLOATS * 4)

// ---------------- device scratch (step vectors transposed [dim][BSZ]) ----------------
__device__ __half g_w1h[(size_t)BSZ * TE * HD];
__device__ __half g_ench[(size_t)BSZ * TE * HD];
__device__ float g_pre1[STEPS * BSZ * HD];
__device__ float g_xs[STEPS * BSZ * (HD / 2)];
__device__ float g_giatt[(size_t)STEPS * G3 * BSZ];  // [step][j][b]
__device__ float g_dbuf[2][HD * BSZ];
__device__ float g_h1buf[2][HD * BSZ];
__device__ float g_h2buf[2][HD * BSZ];
__device__ float g_q[HD * BSZ];
__device__ float g_ddot[HD * BSZ];
__device__ float g_p[HD * BSZ];
__device__ float g_in2[HD * BSZ];
__device__ float g_s[HD * BSZ];
__device__ unsigned g_bar_leaf[8];
__device__ unsigned g_bar_root;
__device__ unsigned g_bar_epoch;

// ---------------- helpers ------------------------------------------------------------
__device__ __forceinline__ float tanh_fast(float x) {
    float y; asm("tanh.approx.f32 %0, %1;" : "=f"(y) : "f"(x)); return y;
}
__device__ __forceinline__ float sigmoidf_(float x) { return 1.f / (1.f + __expf(-x)); }
__device__ __forceinline__ unsigned ld_acq(const unsigned* p) {
    unsigned v; asm volatile("ld.acquire.gpu.b32 %0, [%1];" : "=r"(v) : "l"(p)); return v;
}
__device__ __forceinline__ void gsync(unsigned target)
{
    __syncthreads();
    if (threadIdx.x == 0) {
        __threadfence();
        const int lf = blockIdx.x & 7;
        if (atomicAdd(&g_bar_leaf[lf], 1u) == 15u) {
            g_bar_leaf[lf] = 0u;
            __threadfence();
            if (atomicAdd(&g_bar_root, 1u) == 7u) {
                g_bar_root = 0u;
                __threadfence();
                atomicAdd(&g_bar_epoch, 1u);
            } else {
                while ((int)(ld_acq(&g_bar_epoch) - target) < 0) { }
            }
        } else {
            while ((int)(ld_acq(&g_bar_epoch) - target) < 0) { }
        }
    }
    __syncthreads();
}
__device__ __forceinline__ void fma_h8(const float4& wh, const float* x8, float& acc)
{
    const __half2* p = (const __half2*)&wh;
    const float2 f0 = __half22float2(p[0]), f1 = __half22float2(p[1]);
    const float2 f2 = __half22float2(p[2]), f3 = __half22float2(p[3]);
    acc = fmaf(f0.x, x8[0], acc); acc = fmaf(f0.y, x8[1], acc);
    acc = fmaf(f1.x, x8[2], acc); acc = fmaf(f1.y, x8[3], acc);
    acc = fmaf(f2.x, x8[4], acc); acc = fmaf(f2.y, x8[5], acc);
    acc = fmaf(f3.x, x8[6], acc); acc = fmaf(f3.y, x8[7], acc);
}

// ---------------- staging: src_t [K][128] -> smem [K][32] ----------------------------
__device__ __forceinline__ void stage_t(const float* __restrict__ src, int K,
                                        float* __restrict__ xs)
{
    const int b0 = (blockIdx.x & 3) << 5;
    const int n = K * 8;
    for (int idx = threadIdx.x; idx < n; idx += NTHR) {
        const int k = idx >> 3, q = idx & 7;
        *(float4*)(xs + k * 32 + 4 * q) = *(const float4*)(src + (size_t)k * BSZ + b0 + 4 * q);
    }
}

// ---------------- GRU: smem weights; 16 warps = 8 j x 2 K-halves ---------------------
__device__ void gru_t(const float* __restrict__ gi_t,      // global [768][128] or null
                      const float* __restrict__ WhhS,      // smem 6144 fl
                      const __half* __restrict__ WihS,     // smem 6144 h or null
                      const float* __restrict__ bih, const float* __restrict__ bhh,
                      const float* __restrict__ Hs, const float* __restrict__ Xs,
                      float* __restrict__ Hnew_t, float* __restrict__ Sum_t,
                      float* __restrict__ part)
{
    const int w = threadIdx.x >> 5, lane = threadIdx.x & 31;
    const int wl = w & 7, up = w >> 3;
    const int j = (blockIdx.x >> 2) + (wl << 5);
    const int b = ((blockIdx.x & 3) << 5) + lane;

    const float4* Wr4 = (const float4*)WhhS + wl * 192 + up * 32;
    const float4* Wz4 = Wr4 + 64;
    const float4* Wn4 = Wr4 + 128;
    float hr = 0.f, hz = 0.f, hn = 0.f;
#pragma unroll 8
    for (int k4 = 0; k4 < 32; k4++) {
        const int kk = ((up << 5) + k4) << 2;
        const float4 a = Wr4[k4], c = Wz4[k4], d = Wn4[k4];
        const float h0 = Hs[(kk + 0) * 32 + lane];
        const float h1 = Hs[(kk + 1) * 32 + lane];
        const float h2 = Hs[(kk + 2) * 32 + lane];
        const float h3 = Hs[(kk + 3) * 32 + lane];
        hr = fmaf(a.x, h0, hr); hr = fmaf(a.y, h1, hr);
        hr = fmaf(a.z, h2, hr); hr = fmaf(a.w, h3, hr);
        hz = fmaf(c.x, h0, hz); hz = fmaf(c.y, h1, hz);
        hz = fmaf(c.z, h2, hz); hz = fmaf(c.w, h3, hz);
        hn = fmaf(d.x, h0, hn); hn = fmaf(d.y, h1, hn);
        hn = fmaf(d.z, h2, hn); hn = fmaf(d.w, h3, hn);
    }
    float xr = 0.f, xz = 0.f, xn = 0.f;
    if (WihS) {
        const float4* U4 = (const float4*)WihS;
        const int rb = wl * 96 + up * 16;
#pragma unroll 4
        for (int k8 = 0; k8 < 16; k8++) {
            const int kb = (up << 7) + (k8 << 3);
            float x8[8];
#pragma unroll
            for (int i = 0; i < 8; i++) x8[i] = Xs[(kb + i) * 32 + lane];
            fma_h8(U4[rb + k8], x8, xr);
            fma_h8(U4[rb + 32 + k8], x8, xz);
            fma_h8(U4[rb + 64 + k8], x8, xn);
        }
    }
    if (up) {
        float* pp = part + (wl * 6) * 32 + lane;
        pp[0]   = hr; pp[32]  = hz; pp[64]  = hn;
        pp[96]  = xr; pp[128] = xz; pp[160] = xn;
    }
    __syncthreads();
    if (!up) {
        const float* pp = part + (wl * 6) * 32 + lane;
        hr += pp[0]; hz += pp[32]; hn += pp[64];
        float ir, iz, inn;
        if (gi_t) {
            ir  = gi_t[(size_t)j * BSZ + b];
            iz  = gi_t[(size_t)(j + HD) * BSZ + b];
            inn = gi_t[(size_t)(j + 2 * HD) * BSZ + b];
        } else {
            ir  = xr + pp[96]  + bih[j];
            iz  = xz + pp[128] + bih[j + HD];
            inn = xn + pp[160] + bih[j + 2 * HD];
        }
        const float rg = sigmoidf_(ir + hr + bhh[j]);
        const float zg = sigmoidf_(iz + hz + bhh[j + HD]);
        const float ng = tanhf(inn + rg * (hn + bhh[j + 2 * HD]));
        const float hv = Hs[j * 32 + lane];
        const float val = (1.f - zg) * ng + zg * hv;
        Hnew_t[(size_t)j * BSZ + b] = val;
        if (Sum_t) Sum_t[(size_t)j * BSZ + b] = val + Xs[j * 32 + lane];
    }
    __syncthreads();
}

// ---------------- GEMV (fp16 smem weights): 16 warps = 4 jp x 4 K-splits -------------
__device__ void gemv_h(const __half* __restrict__ WS, const float* __restrict__ bias,
                       const float* __restrict__ Xs, int K,
                       float* __restrict__ Y_t, float* __restrict__ part)
{
    const int w = threadIdx.x >> 5, lane = threadIdx.x & 31;
    const int g = w & 3, ks = w >> 2;
    const int jp = (blockIdx.x >> 2) + (g << 5);
    const int j0 = 2 * jp;
    const int b = ((blockIdx.x & 3) << 5) + lane;
    const int nf4 = K >> 3;            // float4-of-8-halves per row
    const int sl  = nf4 >> 2;          // slice length per ks
    const float4* Wa = (const float4*)WS + (g * 2) * nf4 + ks * sl;
    const float4* Wb = Wa + nf4;
    float a0 = 0.f, a1 = 0.f;
    for (int k8 = 0; k8 < sl; k8++) {
        const int kb = ks * (K >> 2) + (k8 << 3);
        float x8[8];
#pragma unroll
        for (int i = 0; i < 8; i++) x8[i] = Xs[(kb + i) * 32 + lane];
        fma_h8(Wa[k8], x8, a0);
        fma_h8(Wb[k8], x8, a1);
    }
    if (ks) {
        float* pp = part + ((ks - 1) * 4 + g) * 64 + lane;
        pp[0] = a0; pp[32] = a1;
    }
    __syncthreads();
    if (!ks) {
        const float* pp = part + g * 64 + lane;
        a0 += pp[0]  + pp[256] + pp[512];
        a1 += pp[32] + pp[288] + pp[544];
        Y_t[(size_t)j0 * BSZ + b]       = a0 + bias[j0];
        Y_t[(size_t)(j0 + 1) * BSZ + b] = a1 + bias[j0 + 1];
    }
    __syncthreads();
}

// ---------------- G: out rows from smem fp32 weights (zero-padded) -------------------
__device__ void gemv_out(const float* __restrict__ WoutS, const float* __restrict__ bias,
                         const float* __restrict__ Xs, float* __restrict__ outp,
                         float* __restrict__ part)
{
    const int w = threadIdx.x >> 5, lane = threadIdx.x & 31;
    const int g = w & 7, ks = w >> 3;
    const int jp = (blockIdx.x >> 2) + (g << 5);
    const bool valid = jp < 200;
    const int j0 = 2 * jp;
    const int b = ((blockIdx.x & 3) << 5) + lane;
    const float4* Wa = (const float4*)WoutS + (g * 2) * 64 + ks * 32;
    const float4* Wb = Wa + 64;
    float a0 = 0.f, a1 = 0.f;
#pragma unroll 8
    for (int k4 = 0; k4 < 32; k4++) {
        const int kk = ((ks << 5) + k4) << 2;
        const float4 wa = Wa[k4], wb = Wb[k4];
        const float x0 = Xs[(kk + 0) * 32 + lane];
        const float x1 = Xs[(kk + 1) * 32 + lane];
        const float x2 = Xs[(kk + 2) * 32 + lane];
        const float x3 = Xs[(kk + 3) * 32 + lane];
        a0 = fmaf(wa.x, x0, a0); a0 = fmaf(wa.y, x1, a0);
        a0 = fmaf(wa.z, x2, a0); a0 = fmaf(wa.w, x3, a0);
        a1 = fmaf(wb.x, x0, a1); a1 = fmaf(wb.y, x1, a1);
        a1 = fmaf(wb.z, x2, a1); a1 = fmaf(wb.w, x3, a1);
    }
    if (ks) { float* pp = part + g * 64 + lane; pp[0] = a0; pp[32] = a1; }
    __syncthreads();
    if (valid && !ks) {
        const float* pp = part + g * 64 + lane;
        a0 += pp[0]; a1 += pp[32];
        outp[(size_t)b * 80000 + j0]     = a0 + bias[j0];
        outp[(size_t)b * 80000 + j0 + 1] = a1 + bias[j0 + 1];
    }
    __syncthreads();
}

// ---------------- fused attention (block = batch b) ----------------------------------
__device__ void dev_attn(const float* __restrict__ vw, const float* __restrict__ vb,
                         float* smf)
{
    float* qs   = smf;
    float* vs   = smf + 256;
    float* sexp = smf + 512;
    float* red  = smf + 1024;
    float* pacc = smf + 1040;
    const int tid = threadIdx.x, lane = tid & 31, wid = tid >> 5;
    const int b = blockIdx.x;
    const float vb0 = vb[0];

    if (tid < HD) { qs[tid] = g_q[(size_t)tid * BSZ + b]; vs[tid] = vw[tid]; }
    __syncthreads();

    float2 q2[4], v2[4];
#pragma unroll
    for (int m = 0; m < 4; m++) {
        q2[m] = *(const float2*)(qs + 2 * (lane + m * 32));
        v2[m] = *(const float2*)(vs + 2 * (lane + m * 32));
    }
    const __half2* wb = (const __half2*)g_w1h + (size_t)b * TE * (HD / 2);
#pragma unroll 2
    for (int i = 0; i < 32; i++) {
        const int t = wid * 32 + i;
        const __half2* r2 = wb + (size_t)t * (HD / 2) + lane;
        float acc = 0.f;
#pragma unroll
        for (int m = 0; m < 4; m++) {
            float2 ww = __half22float2(r2[m * 32]);
            acc += v2[m].x * tanh_fast(ww.x + q2[m].x)
                 + v2[m].y * tanh_fast(ww.y + q2[m].y);
        }
        for (int o = 16; o; o >>= 1) acc += __shfl_down_sync(0xffffffffu, acc, o);
        if (lane == 0) sexp[t] = acc + vb0;
    }
    __syncthreads();

    float s = sexp[tid];
    float m_ = s;
    for (int o = 16; o; o >>= 1) m_ = fmaxf(m_, __shfl_xor_sync(0xffffffffu, m_, o));
    if (lane == 0) red[wid] = m_;
    __syncthreads();
    float mx = red[0];
#pragma unroll
    for (int k = 1; k < 16; k++) mx = fmaxf(mx, red[k]);
    float e = __expf(s - mx);
    float ss = e;
    for (int o = 16; o; o >>= 1) ss += __shfl_xor_sync(0xffffffffu, ss, o);
    __syncthreads();
    sexp[tid] = e;
    if (lane == 0) red[wid] = ss;
    __syncthreads();
    float sum = red[0];
#pragma unroll
    for (int k = 1; k < 16; k++) sum += red[k];
    const float inv = 1.f / sum;

    const int h2 = tid & 127, tq = tid >> 7;
    const __half2* e2 = (const __half2*)g_ench
                      + ((size_t)b * TE + tq * 128) * (HD / 2) + h2;
    float ax = 0.f, ay = 0.f;
#pragma unroll 8
    for (int tt = 0; tt < 128; tt++) {
        float2 v = __half22float2(e2[(size_t)tt * (HD / 2)]);
        float uu = sexp[tq * 128 + tt];
        ax = fmaf(uu, v.x, ax); ay = fmaf(uu, v.y, ay);
    }
    pacc[tq * 256 + h2 * 2]     = ax;
    pacc[tq * 256 + h2 * 2 + 1] = ay;
    __syncthreads();
    if (tid < HD) {
        float r = pacc[tid] + pacc[256 + tid] + pacc[512 + tid] + pacc[768 + tid];
        g_ddot[(size_t)tid * BSZ + b] = r * inv;
    }
    __syncthreads();
}

// ---------------- prelude tiled GEMM (unchanged) -------------------------------------
__device__ void dev_linear(const float* __restrict__ X, const float* __restrict__ dec,
                           int nf4, const float* __restrict__ W,
                           const float* __restrict__ bias,
                           float* __restrict__ Yf, __half* __restrict__ Yh,
                           int ldy, int relu, int nrt, int ncp, float4* sm4, int tmode)
{
    const int tid = threadIdx.x, lane = tid & 31, wid = tid >> 5;
    const int stride4 = nf4 + 1;
    const int tiles = nrt * ncp;
    for (int t = blockIdx.x; t < tiles; t += GRID) {
        const int rt = t / ncp, cp = t - rt * ncp;
        const long r0 = (long)rt * 32;
        for (int idx = tid; idx < 32 * nf4; idx += NTHR) {
            int row = idx / nf4, c4 = idx - row * nf4;
            long r = r0 + row;
            float4 v;
            if (dec) v = *(const float4*)(dec + (r & 127) * 80000L
                                          + (r >> 7) * (RF * MELD) + c4 * 4);
            else     v = *(const float4*)(X + r * (long)(nf4 * 4) + c4 * 4);
            sm4[row * stride4 + c4] = v;
        }
        __syncthreads();
        const int j0 = cp * 64 + wid * 4;
        const float4* W4 = (const float4*)W + (size_t)j0 * nf4;
        const float4* xr = sm4 + lane * stride4;
        float a0 = bias[j0], a1 = bias[j0 + 1], a2 = bias[j0 + 2], a3 = bias[j0 + 3];
#pragma unroll 4
        for (int k = 0; k < nf4; k++) {
            const float4 x = xr[k];
            const float4 w0 = W4[k];
            a0 = fmaf(w0.x, x.x, a0); a0 = fmaf(w0.y, x.y, a0);
            a0 = fmaf(w0.z, x.z, a0); a0 = fmaf(w0.w, x.w, a0);
            const float4 w1 = W4[nf4 + k];
            a1 = fmaf(w1.x, x.x, a1); a1 = fmaf(w1.y, x.y, a1);
            a1 = fmaf(w1.z, x.z, a1); a1 = fmaf(w1.w, x.w, a1);
            const float4 w2 = W4[2 * nf4 + k];
            a2 = fmaf(w2.x, x.x, a2); a2 = fmaf(w2.y, x.y, a2);
            a2 = fmaf(w2.z, x.z, a2); a2 = fmaf(w2.w, x.w, a2);
            const float4 w3 = W4[3 * nf4 + k];
            a3 = fmaf(w3.x, x.x, a3); a3 = fmaf(w3.y, x.y, a3);
            a3 = fmaf(w3.z, x.z, a3); a3 = fmaf(w3.w, x.w, a3);
        }
        if (relu) {
            a0 = fmaxf(a0, 0.f); a1 = fmaxf(a1, 0.f);
            a2 = fmaxf(a2, 0.f); a3 = fmaxf(a3, 0.f);
        }
        const long r = r0 + lane;
        if (tmode) {
            const size_t baseo = (size_t)(r >> 7) * (G3 * BSZ) + (r & 127);
            Yf[baseo + (size_t)(j0 + 0) * BSZ] = a0;
            Yf[baseo + (size_t)(j0 + 1) * BSZ] = a1;
            Yf[baseo + (size_t)(j0 + 2) * BSZ] = a2;
            Yf[baseo + (size_t)(j0 + 3) * BSZ] = a3;
        } else if (Yh) {
            const long orow = r * (long)ldy + j0;
            Yh[orow] = __float2half(a0);     Yh[orow + 1] = __float2half(a1);
            Yh[orow + 2] = __float2half(a2); Yh[orow + 3] = __float2half(a3);
        } else {
            const long orow = r * (long)ldy + j0;
            Yf[orow] = a0; Yf[orow + 1] = a1; Yf[orow + 2] = a2; Yf[orow + 3] = a3;
        }
        __syncthreads();
    }
}

// ---------------- persistent kernel --------------------------------------------------
__global__ void __launch_bounds__(NTHR, 1)
mel_persist(const float* __restrict__ enc, const float* __restrict__ dec,
            const float* pre_w1, const float* pre_b1,
            const float* pre_w2, const float* pre_b2,
            const float* w1, const float* b1, const float* w2, const float* b2,
            const float* v_w, const float* v_b,
            const float* proj_w, const float* proj_b,
            const float* out_w, const float* out_b,
            const float* att_wih, const float* att_whh,
            const float* att_bih, const float* att_bhh,
            const float* g1_wih, const float* g1_whh,
            const float* g1_bih, const float* g1_bhh,
            const float* g2_wih, const float* g2_whh,
            const float* g2_bih, const float* g2_bhh,
            float* __restrict__ out)
{
    extern __shared__ float smf[];
    float* xs  = smf + F_XS;
    float* hs  = smf + F_HS;
    float* scr = smf + F_SCR;
    __half* hb = (__half*)(smf + F_HALFB);
    const int tid = threadIdx.x;
    const unsigned base = ld_acq(&g_bar_epoch);
    unsigned ep = 0;
#define GS() gsync(base + (++ep))

    // P0: zero states + fp16 enc copy
    {
        const int gtid = blockIdx.x * NTHR + tid;
        for (int i = gtid; i < HD * BSZ; i += GRID * NTHR) {
            g_dbuf[0][i] = 0.f;  g_dbuf[1][i] = 0.f;
            g_h1buf[0][i] = 0.f; g_h1buf[1][i] = 0.f;
            g_h2buf[0][i] = 0.f; g_h2buf[1][i] = 0.f;
        }
        const float4* e4 = (const float4*)enc;
        __half2* o2 = (__half2*)g_ench;
        const int n4 = (BSZ * TE * HD) / 4;
        for (int i = gtid; i < n4; i += GRID * NTHR) {
            const float4 v = e4[i];
            o2[2 * i]     = __floats2half2_rn(v.x, v.y);
            o2[2 * i + 1] = __floats2half2_rn(v.z, v.w);
        }
    }
    // P1..P4 prelude GEMMs (use full smem as staging)
    dev_linear(nullptr, dec, 20, pre_w1, pre_b1, g_pre1, nullptr, HD, 1, 800, 4, (float4*)smf, 0);
    GS();
    dev_linear(g_pre1, nullptr, 64, pre_w2, pre_b2, g_xs, nullptr, 128, 1, 800, 2, (float4*)smf, 0);
    GS();
    dev_linear(g_xs, nullptr, 32, att_wih, att_bih, g_giatt, nullptr, 0, 0, 800, 12, (float4*)smf, 1);
    GS();
    dev_linear(enc, nullptr, 64, w1, b1, nullptr, g_w1h, HD, 0, 2048, 4, (float4*)smf, 0);
    GS();

    // ---- load this block's fixed j-slice weights into smem (once) -------------------
    {
        const int js = blockIdx.x >> 2;
        for (int idx = tid; idx < 6144; idx += NTHR) {
            const int wl = idx / 768, rem = idx - wl * 768;
            const int gr = rem >> 8, k = rem & 255;
            const size_t row = (size_t)(js + (wl << 5) + (gr << 8));
            smf[F_WATT + idx] = att_whh[row * 256 + k];
            smf[F_WG1  + idx] = g1_whh[row * 256 + k];
            smf[F_WG2  + idx] = g2_whh[row * 256 + k];
            hb[H_WIH1 + idx]  = __float2half(g1_wih[row * 256 + k]);
            hb[H_WIH2 + idx]  = __float2half(g2_wih[row * 256 + k]);
        }
        for (int idx = tid; idx < 2048; idx += NTHR) {
            const int g = idx >> 9, r = (idx >> 8) & 1, k = idx & 255;
            const int j = 2 * (js + (g << 5)) + r;
            hb[H_W2 + idx] = __float2half(w2[(size_t)j * 256 + k]);
        }
        for (int idx = tid; idx < 4096; idx += NTHR) {
            const int g = idx >> 10, r = (idx >> 9) & 1, k = idx & 511;
            const int j = 2 * (js + (g << 5)) + r;
            hb[H_PROJ + idx] = __float2half(proj_w[(size_t)j * 512 + k]);
        }
        for (int idx = tid; idx < 4096; idx += NTHR) {
            const int g = idx >> 9, r = (idx >> 8) & 1, k = idx & 255;
            const int jp = js + (g << 5);
            smf[F_WOUT + idx] = (jp < 200) ? out_w[(size_t)(2 * jp + r) * 256 + k] : 0.f;
        }
    }
    __syncthreads();

    for (int i = 0; i < STEPS; i++) {
        const int cur = i & 1, prev = cur ^ 1;

        // A: attention GRU (gi precomputed; Whh from smem)
        stage_t(g_dbuf[prev], 256, xs);
        __syncthreads();
        gru_t(g_giatt + (size_t)i * G3 * BSZ, smf + F_WATT, nullptr,
              nullptr, att_bhh, xs, nullptr, g_dbuf[cur], nullptr, scr);
        GS();
        // B: q = d @ w2^T + b2 (fp16 smem weights)
        stage_t(g_dbuf[cur], 256, xs);
        __syncthreads();
        gemv_h(hb + H_W2, b2, xs, 256, g_q, scr);
        GS();
        // C: attention
        dev_attn(v_w, v_b, scr);
        GS();
        // D: p = [d | ddot] @ proj^T (d still in xs; ddot staged into hs = rows 256..511)
        stage_t(g_ddot, 256, hs);
        __syncthreads();
        gemv_h(hb + H_PROJ, proj_b, xs, 512, g_p, scr);
        GS();
        // E: GRU1; in2 = p + o1
        stage_t(g_p, 256, xs);
        stage_t(g_h1buf[prev], 256, hs);
        __syncthreads();
        gru_t(nullptr, smf + F_WG1, hb + H_WIH1, g1_bih, g1_bhh,
              hs, xs, g_h1buf[cur], g_in2, scr);
        GS();
        // F: GRU2; s = in2 + o2
        stage_t(g_in2, 256, xs);
        stage_t(g_h2buf[prev], 256, hs);
        __syncthreads();
        gru_t(nullptr, smf + F_WG2, hb + H_WIH2, g2_bih, g2_bhh,
              hs, xs, g_h2buf[cur], g_s, scr);
        GS();
        // G: out rows (no grid barrier; next-A write target is disjoint)
        stage_t(g_s, 256, xs);
        __syncthreads();
        gemv_out(smf + F_WOUT, out_b, xs, out + (size_t)i * RF * MELD, scr);
    }
#undef GS
}

// ---------------- host launch --------------------------------------------------------
extern "C" void kernel_launch(void* const* d_in, const int* in_sizes, int n_in,
                              void* d_out, int out_size)
{
    cudaFuncSetAttribute(mel_persist, cudaFuncAttributeMaxDynamicSharedMemorySize,
                         SMEM_BYTES);
    mel_persist<<<GRID, NTHR, SMEM_BYTES>>>(
        (const float*)d_in[0],  (const float*)d_in[1],
        (const float*)d_in[2],  (const float*)d_in[3],
        (const float*)d_in[4],  (const float*)d_in[5],
        (const float*)d_in[6],  (const float*)d_in[7],
        (const float*)d_in[8],  (const float*)d_in[9],
        (const float*)d_in[10], (const float*)d_in[11],
        (const float*)d_in[12], (const float*)d_in[13],
        (const float*)d_in[14], (const float*)d_in[15],
        (const float*)d_in[16], (const float*)d_in[17],
        (const float*)d_in[18], (const float*)d_in[19],
        (const float*)d_in[20], (const float*)d_in[21],
        (const float*)d_in[22], (const float*)d_in[23],
        (const float*)d_in[24], (const float*)d_in[25],
        (const float*)d_in[26], (const float*)d_in[27],
        (float*)d_out);
}